// round 9
// baseline (speedup 1.0000x reference)
#include <cuda_runtime.h>
#include <cstdint>

#define KS   9
#define HID  128
#define LEN  2048
#define ROWS 512       // B*H = 8*64
#define TPB  128
#define TPT  8         // outputs per thread
#define HALF_LEN 1024  // outputs per block (half a row)

typedef unsigned long long ull;

// ---- packed f32x2 helpers (sm_103a) ----
__device__ __forceinline__ ull pack2(float lo, float hi) {
    ull r;
    asm("mov.b64 %0, {%1,%2};" : "=l"(r) : "f"(lo), "f"(hi));
    return r;
}
__device__ __forceinline__ void unpack2(ull v, float& lo, float& hi) {
    asm("mov.b64 {%0,%1}, %2;" : "=f"(lo), "=f"(hi) : "l"(v));
}
__device__ __forceinline__ ull fma2(ull a, ull b, ull c) {
    ull d;
    asm("fma.rn.f32x2 %0, %1, %2, %3;" : "=l"(d) : "l"(a), "l"(b), "l"(c));
    return d;
}
// acc += relu2(h) * w2   (relu on halves in place, then packed FMA)
__device__ __forceinline__ void relu_fma_acc(ull& acc, ull h, ull w2d) {
    asm("{\n\t"
        ".reg .f32 lo, hi;\n\t"
        "mov.b64 {lo, hi}, %1;\n\t"
        "max.f32 lo, lo, 0f00000000;\n\t"
        "max.f32 hi, hi, 0f00000000;\n\t"
        "mov.b64 %1, {lo, hi};\n\t"
        "fma.rn.f32x2 %0, %1, %2, %0;\n\t"
        "}"
        : "+l"(acc), "+l"(h) : "l"(w2d));
}

__global__ __launch_bounds__(TPB, 8)
void simconv1d_kernel(const float* __restrict__ x,
                      const float* __restrict__ W1,   // [9][128] (k, d)
                      const float* __restrict__ b1,   // [128]
                      const float* __restrict__ W2,   // [128]
                      const float* __restrict__ b2,   // [1]
                      float* __restrict__ y) {
    // Per-d packed operand record, 16B-aligned, 6 x ulonglong2 = 12 u64 slots:
    // {w0,w1},{w2,w3},{w4,w5},{w6,w7},{w8,bias},{w2dup,pad}
    __shared__ ulonglong2 sP[HID][6];

    ull* sPu = reinterpret_cast<ull*>(sP);
    const int tid = threadIdx.x;

    for (int i = tid; i < KS * HID; i += TPB) {
        int k = i / HID;            // 0..8
        int d = i - k * HID;
        float w = W1[i];
        sPu[d * 12 + k] = pack2(w, w);
    }
    if (tid < HID) {
        float b = b1[tid];
        float w2 = W2[tid];
        sPu[tid * 12 + 9]  = pack2(b, b);
        sPu[tid * 12 + 10] = pack2(w2, w2);
        sPu[tid * 12 + 11] = 0ull;
    }
    __syncthreads();

    const int row  = blockIdx.x >> 1;
    const int half = blockIdx.x & 1;
    const float* xr = x + row * LEN;
    const int t0 = half * HALF_LEN + tid * TPT;   // first output position

    // Load the 16 x values covering outputs [t0, t0+8) with taps o-4..o+4,
    // packing overlapping adjacent pairs on the fly: xp[i]=(x[i],x[i+1]).
    // Rolling-scalar pack keeps only 2 floats live instead of a 16-float array.
    ull xp[TPT + KS - 2];   // 15
    {
        float prev, cur;
        {
            int gi = t0 - 4;
            prev = (gi >= 0 && gi < LEN) ? __ldg(xr + gi) : 0.f;
        }
        #pragma unroll
        for (int i = 0; i < TPT + KS - 2; i++) {
            int gi = t0 - 3 + i;
            cur = (gi >= 0 && gi < LEN) ? __ldg(xr + gi) : 0.f;
            xp[i] = pack2(prev, cur);
            prev = cur;
        }
    }

    // Packed accumulators, pre-seeded with the output bias b2.
    const float bias2 = __ldg(b2);
    ull acc2[TPT / 2];
    #pragma unroll
    for (int p = 0; p < TPT / 2; p++) acc2[p] = pack2(bias2, bias2);

    #pragma unroll 2
    for (int d = 0; d < HID; d++) {
        // 6 broadcast LDS.128 (conflict-free, N=1) deliver 9 weights+bias+w2
        ulonglong2 p0 = sP[d][0];
        ulonglong2 p1 = sP[d][1];
        ulonglong2 p2 = sP[d][2];
        ulonglong2 p3 = sP[d][3];
        ulonglong2 p4 = sP[d][4];
        ulonglong2 p5 = sP[d][5];

        // 4 independent packed 9-deep FMA chains, fused relu+accumulate tail
        #pragma unroll
        for (int p = 0; p < TPT / 2; p++) {
            ull h2 = p4.y;                         // bias1 (dup'd)
            h2 = fma2(xp[2 * p + 0], p0.x, h2);
            h2 = fma2(xp[2 * p + 1], p0.y, h2);
            h2 = fma2(xp[2 * p + 2], p1.x, h2);
            h2 = fma2(xp[2 * p + 3], p1.y, h2);
            h2 = fma2(xp[2 * p + 4], p2.x, h2);
            h2 = fma2(xp[2 * p + 5], p2.y, h2);
            h2 = fma2(xp[2 * p + 6], p3.x, h2);
            h2 = fma2(xp[2 * p + 7], p3.y, h2);
            h2 = fma2(xp[2 * p + 8], p4.x, h2);
            relu_fma_acc(acc2[p], h2, p5.x);
        }
    }

    float* yr = y + row * LEN + t0;
    #pragma unroll
    for (int p = 0; p < TPT / 2; p++) {
        float a0, a1;
        unpack2(acc2[p], a0, a1);
        yr[2 * p]     = a0;
        yr[2 * p + 1] = a1;
    }
}

extern "C" void kernel_launch(void* const* d_in, const int* in_sizes, int n_in,
                              void* d_out, int out_size) {
    const float* x  = (const float*)d_in[0];
    const float* W1 = (const float*)d_in[1];
    const float* b1 = (const float*)d_in[2];
    const float* W2 = (const float*)d_in[3];
    const float* b2 = (const float*)d_in[4];
    float* y = (float*)d_out;
    simconv1d_kernel<<<ROWS * 2, TPB>>>(x, W1, b1, W2, b2, y);
}

// round 16
// speedup vs baseline: 1.0847x; 1.0847x over previous
#include <cuda_runtime.h>
#include <cstdint>

#define KS   9
#define HID  128
#define LEN  2048
#define ROWS 512       // B*H = 8*64
#define TPB  128
#define TPT  8         // outputs per thread
#define HALF_LEN 1024  // outputs per block (half a row)

typedef unsigned long long ull;

// ---- packed f32x2 helpers (sm_103a) ----
__device__ __forceinline__ ull pack2(float lo, float hi) {
    ull r;
    asm("mov.b64 %0, {%1,%2};" : "=l"(r) : "f"(lo), "f"(hi));
    return r;
}
__device__ __forceinline__ void unpack2(ull v, float& lo, float& hi) {
    asm("mov.b64 {%0,%1}, %2;" : "=f"(lo), "=f"(hi) : "l"(v));
}
__device__ __forceinline__ ull fma2(ull a, ull b, ull c) {
    ull d;
    asm("fma.rn.f32x2 %0, %1, %2, %3;" : "=l"(d) : "l"(a), "l"(b), "l"(c));
    return d;
}
// acc += relu2(h) * w2   (relu on halves in place, then packed FMA)
__device__ __forceinline__ void relu_fma_acc(ull& acc, ull h, ull w2d) {
    asm("{\n\t"
        ".reg .f32 lo, hi;\n\t"
        "mov.b64 {lo, hi}, %1;\n\t"
        "max.f32 lo, lo, 0f00000000;\n\t"
        "max.f32 hi, hi, 0f00000000;\n\t"
        "mov.b64 %1, {lo, hi};\n\t"
        "fma.rn.f32x2 %0, %1, %2, %0;\n\t"
        "}"
        : "+l"(acc), "+l"(h) : "l"(w2d));
}

__global__ __launch_bounds__(TPB, 5)
void simconv1d_kernel(const float* __restrict__ x,
                      const float* __restrict__ W1,   // [9][128] (k, d)
                      const float* __restrict__ b1,   // [128]
                      const float* __restrict__ W2,   // [128]
                      const float* __restrict__ b2,   // [1]
                      float* __restrict__ y) {
    // Per-d packed operand record, 16B-aligned, 6 x ulonglong2 = 12 u64 slots:
    // {w0,w1},{w2,w3},{w4,w5},{w6,w7},{w8,bias},{w2dup,pad}
    __shared__ ulonglong2 sP[HID][6];

    ull* sPu = reinterpret_cast<ull*>(sP);
    const int tid = threadIdx.x;

    for (int i = tid; i < KS * HID; i += TPB) {
        int k = i / HID;            // 0..8
        int d = i - k * HID;
        float w = W1[i];
        sPu[d * 12 + k] = pack2(w, w);
    }
    if (tid < HID) {
        float b = b1[tid];
        float w2 = W2[tid];
        sPu[tid * 12 + 9]  = pack2(b, b);
        sPu[tid * 12 + 10] = pack2(w2, w2);
        sPu[tid * 12 + 11] = 0ull;
    }
    __syncthreads();

    const int row  = blockIdx.x >> 1;
    const int half = blockIdx.x & 1;
    const float* xr = x + row * LEN;
    const int t0 = half * HALF_LEN + tid * TPT;   // first output position

    // Load the 16 x values covering outputs [t0, t0+8) with taps o-4..o+4,
    // packing overlapping adjacent pairs: xp[i]=(x[i],x[i+1]).
    ull xp[TPT + KS - 2];   // 15
    {
        float xv[TPT + KS - 1];            // 16 (dead after packing)
        #pragma unroll
        for (int i = 0; i < TPT + KS - 1; i++) {
            int gi = t0 - 4 + i;
            xv[i] = (gi >= 0 && gi < LEN) ? __ldg(xr + gi) : 0.f;
        }
        #pragma unroll
        for (int i = 0; i < TPT + KS - 2; i++) xp[i] = pack2(xv[i], xv[i + 1]);
    }

    // Packed accumulators, pre-seeded with the output bias b2.
    const float bias2 = __ldg(b2);
    ull acc2[TPT / 2];
    #pragma unroll
    for (int p = 0; p < TPT / 2; p++) acc2[p] = pack2(bias2, bias2);

    // Software-pipelined weight record: prefetch d+1 while computing d.
    ulonglong2 c0 = sP[0][0], c1 = sP[0][1], c2 = sP[0][2],
               c3 = sP[0][3], c4 = sP[0][4], c5 = sP[0][5];

    #pragma unroll 2
    for (int d = 0; d < HID; d++) {
        // prefetch next iteration's 6 broadcast LDS.128 (conflict-free)
        int dn = (d + 1) & (HID - 1);
        ulonglong2 n0 = sP[dn][0], n1 = sP[dn][1], n2 = sP[dn][2],
                   n3 = sP[dn][3], n4 = sP[dn][4], n5 = sP[dn][5];

        // 4 independent packed 9-deep FMA chains, fused relu+accumulate tail
        #pragma unroll
        for (int p = 0; p < TPT / 2; p++) {
            ull h2 = c4.y;                         // bias1 (dup'd)
            h2 = fma2(xp[2 * p + 0], c0.x, h2);
            h2 = fma2(xp[2 * p + 1], c0.y, h2);
            h2 = fma2(xp[2 * p + 2], c1.x, h2);
            h2 = fma2(xp[2 * p + 3], c1.y, h2);
            h2 = fma2(xp[2 * p + 4], c2.x, h2);
            h2 = fma2(xp[2 * p + 5], c2.y, h2);
            h2 = fma2(xp[2 * p + 6], c3.x, h2);
            h2 = fma2(xp[2 * p + 7], c3.y, h2);
            h2 = fma2(xp[2 * p + 8], c4.x, h2);
            relu_fma_acc(acc2[p], h2, c5.x);
        }

        c0 = n0; c1 = n1; c2 = n2; c3 = n3; c4 = n4; c5 = n5;
    }

    float* yr = y + row * LEN + t0;
    #pragma unroll
    for (int p = 0; p < TPT / 2; p++) {
        float a0, a1;
        unpack2(acc2[p], a0, a1);
        yr[2 * p]     = a0;
        yr[2 * p + 1] = a1;
    }
}

extern "C" void kernel_launch(void* const* d_in, const int* in_sizes, int n_in,
                              void* d_out, int out_size) {
    const float* x  = (const float*)d_in[0];
    const float* W1 = (const float*)d_in[1];
    const float* b1 = (const float*)d_in[2];
    const float* W2 = (const float*)d_in[3];
    const float* b2 = (const float*)d_in[4];
    float* y = (float*)d_out;
    simconv1d_kernel<<<ROWS * 2, TPB>>>(x, W1, b1, W2, b2, y);
}